// round 1
// baseline (speedup 1.0000x reference)
#include <cuda_runtime.h>
#include <cuda_bf16.h>

// ShiftingLayer: out[b,d,c] = sum_s exp(-(s - center[b,d])^2) / AMP * in[b,s,c]
//   center[b,d] = (d+1 + w[b,d]) * (S/D),  s = 1..S (1-indexed)
// Gaussian with width 1 -> only |s - center| <= ~8 matters (exp(-64) ~ 1.6e-28).
// Strategy: one block per (b, tile of 8 d's). Union window of the 8 centers is
// staged as shared weights; each input element is loaded once and accumulated
// into 8 register accumulators (8x L2-traffic reduction vs per-d gather).

#define B_ 16
#define S_ 4096
#define C_ 256
#define D_ 1024

constexpr int   DT      = 8;          // d's per block
constexpr int   CHUNK   = 64;         // staged s-rows per iteration
constexpr int   RAD     = 8;          // Gaussian support radius (exp(-64) negligible)
constexpr float SCALE   = (float)S_ / (float)D_;   // 4.0
constexpr float INV_AMP = 1.0f / 1.772637204826652f;

__global__ __launch_bounds__(256, 1)
void ShiftingLayer_53798760349850_kernel(const float* __restrict__ in,
                                         const float* __restrict__ wts,
                                         float* __restrict__ out) {
    __shared__ float s_center[DT];
    __shared__ float s_w[DT][CHUNK];
    __shared__ int   s_range[2];

    const int tid = threadIdx.x;            // channel c (0..255)
    const int b   = blockIdx.x / (D_ / DT);
    const int d0  = (blockIdx.x % (D_ / DT)) * DT;

    // Per-d Gaussian centers (1-indexed s space)
    if (tid < DT) {
        float c = ((float)(d0 + tid + 1) + wts[b * D_ + d0 + tid]) * SCALE;
        s_center[tid] = c;
    }
    __syncthreads();

    if (tid == 0) {
        float mn = s_center[0], mx = s_center[0];
#pragma unroll
        for (int j = 1; j < DT; j++) {
            mn = fminf(mn, s_center[j]);
            mx = fmaxf(mx, s_center[j]);
        }
        int slo = (int)floorf(mn) - RAD;
        int shi = (int)ceilf(mx) + RAD;
        if (slo < 1)  slo = 1;      // reference only sums s in [1, S]
        if (shi > S_) shi = S_;
        s_range[0] = slo;
        s_range[1] = shi;
    }
    __syncthreads();

    const int slo = s_range[0];
    const int shi = s_range[1];

    float center[DT];
#pragma unroll
    for (int j = 0; j < DT; j++) center[j] = s_center[j];

    float acc[DT];
#pragma unroll
    for (int j = 0; j < DT; j++) acc[j] = 0.0f;

    const float* inb = in + (size_t)b * S_ * C_ + tid;

    for (int sbase = slo; sbase <= shi; sbase += CHUNK) {
        const int len = min(CHUNK, shi - sbase + 1);

        __syncthreads();
        // Stage weights for this chunk: DT*CHUNK values, 2 per thread.
        for (int idx = tid; idx < DT * CHUNK; idx += 256) {
            int   j    = idx / CHUNK;
            int   si   = idx - j * CHUNK;
            float diff = (float)(sbase + si) - center[j];
            s_w[j][si] = __expf(-diff * diff);   // underflows to 0 far out: exact enough
        }
        __syncthreads();

#pragma unroll 4
        for (int si = 0; si < len; si++) {
            float x = inb[(size_t)(sbase + si - 1) * C_];  // s is 1-indexed
#pragma unroll
            for (int j = 0; j < DT; j++)
                acc[j] = fmaf(s_w[j][si], x, acc[j]);
        }
    }

    float* outb = out + ((size_t)b * D_ + d0) * C_ + tid;
#pragma unroll
    for (int j = 0; j < DT; j++)
        outb[(size_t)j * C_] = acc[j] * INV_AMP;
}

extern "C" void kernel_launch(void* const* d_in, const int* in_sizes, int n_in,
                              void* d_out, int out_size) {
    const float* in  = (const float*)d_in[0];   // (16, 4096, 256) f32
    const float* wts = (const float*)d_in[1];   // (16, 1024) f32
    float*       out = (float*)d_out;           // (16, 1024, 256) f32

    dim3 grid(B_ * (D_ / DT));
    dim3 block(256);
    ShiftingLayer_53798760349850_kernel<<<grid, block>>>(in, wts, out);
}

// round 4
// speedup vs baseline: 3.3540x; 3.3540x over previous
#include <cuda_runtime.h>
#include <cuda_bf16.h>

// ShiftingLayer: out[b,d,c] = (1/AMP) * sum_s exp(-(s - center[b,d])^2) * in[b,s,c]
//   center[b,d] = (d+1 + w[b,d]) * (S/D), s = 1..S (1-indexed).
//
// Per-d private window: only s in [floor(c)-3, floor(c)+4] matter (K=8);
// omitted weights <= exp(-16) ~ 1.1e-7 relative -> negligible vs 1e-3 threshold.
// float4 vectorization: thread = channel quad; LDG.128 input, LDS.128 weights.

#define B_ 16
#define S_ 4096
#define C_ 256
#define D_ 1024

constexpr int   DT      = 16;         // d's per block
constexpr int   K_      = 8;          // window rows per d
constexpr int   RAD     = 3;          // floor(c)-RAD .. floor(c)-RAD+K-1
constexpr float SCALE   = (float)S_ / (float)D_;   // 4.0
constexpr float INV_AMP = 1.0f / 1.772637204826652f;

__global__ __launch_bounds__(256, 4)
void ShiftingLayer_53798760349850_kernel(const float* __restrict__ in,
                                         const float* __restrict__ wts,
                                         float* __restrict__ out) {
    __shared__ __align__(16) float s_w[DT][K_];   // per-d Gaussian weights
    __shared__ int s_ss[DT];                      // per-d window start (1-indexed s)

    const int tid = threadIdx.x;
    const int b   = blockIdx.x / (D_ / DT);
    const int d0  = (blockIdx.x % (D_ / DT)) * DT;

    // Precompute windows + weights: DT*K_ = 128 threads, one weight each.
    if (tid < DT * K_) {
        const int j = tid >> 3;         // d within tile
        const int k = tid & 7;          // row within window
        const float c = ((float)(d0 + j + 1) + wts[b * D_ + d0 + j]) * SCALE;
        int ss = (int)floorf(c) - RAD;  // window start in 1-indexed s space
        if (ss < 1) ss = 1;
        if (ss > S_ - K_ + 1) ss = S_ - K_ + 1;
        const float diff = (float)(ss + k) - c;
        s_w[j][k] = __expf(-diff * diff);
        if (k == 0) s_ss[j] = ss;
    }
    __syncthreads();

    const int cq = tid & 63;            // channel quad: channels 4*cq .. 4*cq+3
    const int g  = tid >> 6;            // d-group 0..3 (4 d's each)

    const float4* inb = reinterpret_cast<const float4*>(in) +
                        (size_t)b * S_ * (C_ / 4) + cq;
    float4* outb = reinterpret_cast<float4*>(out) +
                   ((size_t)b * D_ + d0) * (C_ / 4) + cq;

#pragma unroll
    for (int jj = 0; jj < 4; jj++) {
        const int j  = g * 4 + jj;
        const int ss = s_ss[j];

        // 8 weights via two LDS.128
        const float4 w03 = *reinterpret_cast<const float4*>(&s_w[j][0]);
        const float4 w47 = *reinterpret_cast<const float4*>(&s_w[j][4]);
        const float wk[8] = {w03.x, w03.y, w03.z, w03.w,
                             w47.x, w47.y, w47.z, w47.w};

        const float4* p = inb + (size_t)(ss - 1) * (C_ / 4);

        float4 acc = make_float4(0.f, 0.f, 0.f, 0.f);
#pragma unroll
        for (int k = 0; k < K_; k++) {
            const float4 x = p[(size_t)k * (C_ / 4)];
            const float  w = wk[k];
            acc.x = fmaf(w, x.x, acc.x);
            acc.y = fmaf(w, x.y, acc.y);
            acc.z = fmaf(w, x.z, acc.z);
            acc.w = fmaf(w, x.w, acc.w);
        }

        acc.x *= INV_AMP; acc.y *= INV_AMP; acc.z *= INV_AMP; acc.w *= INV_AMP;
        outb[(size_t)j * (C_ / 4)] = acc;
    }
}

extern "C" void kernel_launch(void* const* d_in, const int* in_sizes, int n_in,
                              void* d_out, int out_size) {
    const float* in  = (const float*)d_in[0];   // (16, 4096, 256) f32
    const float* wts = (const float*)d_in[1];   // (16, 1024) f32
    float*       out = (float*)d_out;           // (16, 1024, 256) f32

    dim3 grid(B_ * (D_ / DT));
    dim3 block(256);
    ShiftingLayer_53798760349850_kernel<<<grid, block>>>(in, wts, out);
}